// round 10
// baseline (speedup 1.0000x reference)
#include <cuda_runtime.h>
#include <cuda_bf16.h>
#include <cstdint>

#define B_    8
#define N_    2048
#define FIN_  128
#define FOUT_ 64
#define TJ    64
#define NT    (N_ / TJ)      // 32 tiles
#define NSPL  4              // j-splits
#define NTS   (NT / NSPL)    // 8 tiles per split
#define MR    128            // i-rows per CTA
#define LOG2E 1.4426950408889634f

// ---------------- global scratch (no allocations allowed) ----------------
__device__ __align__(16) float         g_s1[B_ * N_];                // pre-scaled by LOG2E
__device__ __align__(16) float         g_s2[B_ * N_];                // pre-scaled by LOG2E
__device__ __align__(16) __nv_bfloat16 g_hT_hi[B_ * FOUT_ * N_];     // [b][f][n]
__device__ __align__(16) __nv_bfloat16 g_hT_lo[B_ * FOUT_ * N_];
__device__ __align__(16) float         g_pd[NSPL * B_ * N_ * FOUT_]; // partial D (16MB)
__device__ __align__(16) float         g_pl[NSPL * B_ * N_];         // partial l

// ---------------- helpers ----------------
__device__ __forceinline__ uint32_t pack_bf16(float a, float b) {
    __nv_bfloat162 t = __float22bfloat162_rn(make_float2(a, b));
    return *reinterpret_cast<uint32_t*>(&t);
}
// lo residual pair given the packed hi pair
__device__ __forceinline__ uint32_t lo_pack(float a, float b, uint32_t hi) {
    const float ha = __uint_as_float(hi << 16);
    const float hb = __uint_as_float(hi & 0xFFFF0000u);
    return pack_bf16(a - ha, b - hb);
}
__device__ __forceinline__ void cp16(uint32_t s, const void* g) {
    asm volatile("cp.async.cg.shared.global [%0], [%1], 16;" :: "r"(s), "l"(g));
}
__device__ __forceinline__ void cp_commit() {
    asm volatile("cp.async.commit_group;" ::: "memory");
}
__device__ __forceinline__ void cp_wait0() {
    asm volatile("cp.async.wait_group 0;" ::: "memory");
}
__device__ __forceinline__ uint32_t smem_u32(const void* p) {
    uint32_t a;
    asm("{ .reg .u64 t; cvta.to.shared.u64 t, %1; cvt.u32.u64 %0, t; }" : "=r"(a) : "l"(p));
    return a;
}
// m16n8k16 bf16 MMA, fp32 accumulate in place
__device__ __forceinline__ void mma16816(float* d, const uint32_t* a,
                                         uint32_t b0, uint32_t b1) {
    asm volatile(
        "mma.sync.aligned.m16n8k16.row.col.f32.bf16.bf16.f32 "
        "{%0,%1,%2,%3}, {%4,%5,%6,%7}, {%8,%9}, {%0,%1,%2,%3};"
        : "+f"(d[0]), "+f"(d[1]), "+f"(d[2]), "+f"(d[3])
        : "r"(a[0]), "r"(a[1]), "r"(a[2]), "r"(a[3]), "r"(b0), "r"(b1));
}
// masked softmax numerator; e is pre-scaled by LOG2E
__device__ __forceinline__ float pv(int av, float e) {
    e = fmaxf(e, 0.2f * e);                  // leaky_relu commutes with >0 scale
    float r;
    asm("ex2.approx.ftz.f32 %0, %1;" : "=f"(r) : "f"(e));
    return av ? r : 0.f;
}

// ---------------------------------------------------------------------------
// Kernel 1: h = x@W -> hT_hi/hT_lo (bf16, [b][f][n]) + s1,s2 (pre-scaled LOG2E)
// 256 threads, 32 rows/block, 48KB smem -> 4 CTAs/SM, grid 512.
// ---------------------------------------------------------------------------
__global__ void __launch_bounds__(256)
gat_h_kernel(const float* __restrict__ x,
             const float* __restrict__ W,
             const float* __restrict__ a) {
    extern __shared__ float sm1[];
    float* Wsm = sm1;            // [128*64]  32KB
    float* xsm = sm1 + 8192;     // [32*128]  16KB
    float* hsm = xsm;            // reuse: [32][69]

    const int tid   = threadIdx.x;
    const int row0g = blockIdx.x * 32;
    const int b     = row0g >> 11;
    const int n0    = row0g & (N_ - 1);

    {
        const float4* src = (const float4*)W;
        float4* dst = (float4*)Wsm;
#pragma unroll
        for (int i = 0; i < 8; i++) dst[tid + 256 * i] = src[tid + 256 * i];
    }
    {
        const float4* src = (const float4*)(x + (size_t)row0g * FIN_);
        float4* dst = (float4*)xsm;
#pragma unroll
        for (int i = 0; i < 4; i++) dst[tid + 256 * i] = src[tid + 256 * i];
    }
    __syncthreads();

    const int r  = tid >> 4;      // 0..15
    const int cg = tid & 15;

    float4 acc0 = make_float4(0.f, 0.f, 0.f, 0.f);
    float4 acc1 = make_float4(0.f, 0.f, 0.f, 0.f);
#pragma unroll 8
    for (int k4 = 0; k4 < FIN_; k4 += 4) {
        const float4 xa = *(const float4*)(xsm + r * FIN_ + k4);
        const float4 xb = *(const float4*)(xsm + (r + 16) * FIN_ + k4);
        const float* xap = (const float*)&xa;
        const float* xbp = (const float*)&xb;
#pragma unroll
        for (int kk = 0; kk < 4; kk++) {
            const float4 w4 = *(const float4*)(Wsm + (k4 + kk) * FOUT_ + cg * 4);
            const float x0 = xap[kk], x1 = xbp[kk];
            acc0.x += x0 * w4.x; acc0.y += x0 * w4.y;
            acc0.z += x0 * w4.z; acc0.w += x0 * w4.w;
            acc1.x += x1 * w4.x; acc1.y += x1 * w4.y;
            acc1.z += x1 * w4.z; acc1.w += x1 * w4.w;
        }
    }

    const float4 a1 = *(const float4*)(a + cg * 4);
    const float4 a2 = *(const float4*)(a + FOUT_ + cg * 4);
#pragma unroll
    for (int half = 0; half < 2; half++) {
        const float4 acc = half ? acc1 : acc0;
        const int row = row0g + half * 16 + r;
        float s1 = acc.x * a1.x + acc.y * a1.y + acc.z * a1.z + acc.w * a1.w;
        float s2 = acc.x * a2.x + acc.y * a2.y + acc.z * a2.z + acc.w * a2.w;
#pragma unroll
        for (int m = 8; m >= 1; m >>= 1) {
            s1 += __shfl_xor_sync(0xffffffffu, s1, m);
            s2 += __shfl_xor_sync(0xffffffffu, s2, m);
        }
        if (cg == 0) { g_s1[row] = s1 * LOG2E; g_s2[row] = s2 * LOG2E; }
    }

    __syncthreads();     // xsm reads done; reuse as hsm [32][69]
    {
        float* hp0 = hsm + r * 69 + cg * 4;
        float* hp1 = hsm + (r + 16) * 69 + cg * 4;
        hp0[0] = acc0.x; hp0[1] = acc0.y; hp0[2] = acc0.z; hp0[3] = acc0.w;
        hp1[0] = acc1.x; hp1[1] = acc1.y; hp1[2] = acc1.z; hp1[3] = acc1.w;
    }
    __syncthreads();

    // transpose + hi/lo bf16 split: thread -> (f = tid>>2, 8 consecutive n)
    const int f  = tid >> 2;      // 0..63
    const int jq = tid & 3;
    float v[8];
#pragma unroll
    for (int u = 0; u < 8; u++) v[u] = hsm[(jq * 8 + u) * 69 + f];

    uint4 hiv, lov;
    uint32_t* hp = (uint32_t*)&hiv;
    uint32_t* lp = (uint32_t*)&lov;
#pragma unroll
    for (int q = 0; q < 4; q++) {
        const float va = v[2 * q], vb = v[2 * q + 1];
        hp[q] = pack_bf16(va, vb);
        lp[q] = lo_pack(va, vb, hp[q]);
    }
    const size_t o = ((size_t)(b * FOUT_ + f)) * N_ + n0 + jq * 8;
    *(uint4*)(g_hT_hi + o) = hiv;
    *(uint4*)(g_hT_lo + o) = lov;
}

// ---------------------------------------------------------------------------
// Kernel 2: fused mask/softmax (no-max) -> HMMA hi/lo P·V, j-split partials
// 256 threads = 8 warps x 16 i-rows; grid (16, 8, 4); 3 CTAs/SM target.
// smem (bytes):
#define HH_OFF   0u          // hT_hi [2][64][72] bf16  (18432; row stride 144B)
#define HL_OFF   18432u      // hT_lo                    (18432)
#define ADJ_OFF  36864u      // adj   [2][128][68] u8    (17408)
#define S2_OFF   54272u      // s2    [2][64] f32        (512)
#define SMEM2    54784u
// ---------------------------------------------------------------------------
__global__ void __launch_bounds__(256, 3)
gat_attn_kernel(const int* __restrict__ adj) {
    extern __shared__ char smem[];
    const uint32_t sb = smem_u32(smem);

    const int b    = blockIdx.y;
    const int row0 = blockIdx.x * MR;
    const int js   = blockIdx.z;
    const int t0   = js * NTS;
    const int tid  = threadIdx.x;
    const int w    = tid >> 5;
    const int lane = tid & 31;
    const int g    = lane >> 2;                 // 0..7 (row in frag)
    const int qt   = lane & 3;                  // 0..3 (k group in frag)

    const int* adjB = adj + (size_t)b * N_ * N_;

    // prefetch tile t into buffer buf:
    //  - hT hi/lo + s2 via cp.async (waited with cp_wait0 next iteration)
    //  - adj via LDG int4 -> byte-pack -> STS (visible after next barrier)
    auto prefetch = [&](int t, int buf) {
        const uint32_t hb = sb + (uint32_t)buf * 9216u;
#pragma unroll
        for (int k = 0; k < 2; k++) {
            const int c = tid + 256 * k;        // 512 chunks of 16B
            const int f = c >> 3, jc = c & 7;
            const size_t go = ((size_t)(b * FOUT_ + f)) * N_ + t * TJ + jc * 8;
            const uint32_t so = (uint32_t)(f * 144 + jc * 16);
            cp16(hb + HH_OFF + so, g_hT_hi + go);
            cp16(hb + HL_OFF + so, g_hT_lo + go);
        }
        if (tid < 16)
            cp16(sb + S2_OFF + (uint32_t)buf * 256u + tid * 16,
                 g_s2 + b * N_ + t * TJ + tid * 4);

        char* ad = smem + ADJ_OFF + buf * 8704;
#pragma unroll
        for (int k = 0; k < 8; k++) {
            const int c   = tid + 256 * k;      // 2048 chunks of 4 ints
            const int rr  = c >> 4, cc4 = (c & 15) * 4;
            const int4 vv = *(const int4*)(adjB + (size_t)(row0 + rr) * N_ + t * TJ + cc4);
            const uint32_t pk = (uint32_t)vv.x | ((uint32_t)vv.y << 8) |
                                ((uint32_t)vv.z << 16) | ((uint32_t)vv.w << 24);
            *(uint32_t*)(ad + rr * 68 + cc4) = pk;
        }
    };

    prefetch(t0, 0);
    cp_commit();

    const int i0 = w * 16 + g;          // local row
    const int i1 = i0 + 8;
    const float s10 = g_s1[b * N_ + row0 + i0];
    const float s11 = g_s1[b * N_ + row0 + i1];

    float accs[8][4];
#pragma unroll
    for (int nc = 0; nc < 8; nc++)
#pragma unroll
        for (int q = 0; q < 4; q++) accs[nc][q] = 0.f;
    float l0 = 0.f, l1 = 0.f;

    for (int tt = 0; tt < NTS; tt++) {
        cp_wait0();                     // my cp.async for tile tt landed
        __syncthreads();                // everyone's data (cp + STS) visible;
                                        // buffer (tt+1)&1 now free for writers
        if (tt + 1 < NTS) { prefetch(t0 + tt + 1, (tt + 1) & 1); cp_commit(); }

        const unsigned char* adjt =
            (const unsigned char*)(smem + ADJ_OFF + (tt & 1) * 8704);
        const float* s2t = (const float*)(smem + S2_OFF + (tt & 1) * 256);
        const char*  hh  = smem + HH_OFF + (tt & 1) * 9216;
        const char*  hl  = smem + HL_OFF + (tt & 1) * 9216;

#pragma unroll
        for (int kc = 0; kc < 4; kc++) {
            // ---- Phase A(kc): p into A-fragment registers (hi + lo) ----
            const int jb = kc * 16 + 2 * qt;
            const float2 s2a = *(const float2*)(s2t + jb);
            const float2 s2b = *(const float2*)(s2t + jb + 8);
            const unsigned short m00 = *(const unsigned short*)(adjt + i0 * 68 + jb);
            const unsigned short m08 = *(const unsigned short*)(adjt + i0 * 68 + jb + 8);
            const unsigned short m10 = *(const unsigned short*)(adjt + i1 * 68 + jb);
            const unsigned short m18 = *(const unsigned short*)(adjt + i1 * 68 + jb + 8);

            const float p00 = pv(m00 & 255, s10 + s2a.x);
            const float p01 = pv(m00 >> 8,  s10 + s2a.y);
            const float p02 = pv(m08 & 255, s10 + s2b.x);
            const float p03 = pv(m08 >> 8,  s10 + s2b.y);
            const float p10 = pv(m10 & 255, s11 + s2a.x);
            const float p11 = pv(m10 >> 8,  s11 + s2a.y);
            const float p12 = pv(m18 & 255, s11 + s2b.x);
            const float p13 = pv(m18 >> 8,  s11 + s2b.y);

            l0 += (p00 + p01) + (p02 + p03);
            l1 += (p10 + p11) + (p12 + p13);

            uint32_t aH[4], aL[4];
            aH[0] = pack_bf16(p00, p01);  aL[0] = lo_pack(p00, p01, aH[0]);
            aH[1] = pack_bf16(p10, p11);  aL[1] = lo_pack(p10, p11, aH[1]);
            aH[2] = pack_bf16(p02, p03);  aL[2] = lo_pack(p02, p03, aH[2]);
            aH[3] = pack_bf16(p12, p13);  aL[3] = lo_pack(p12, p13, aH[3]);

            // ---- Phase B(kc): D += P_hi·H_hi + P_lo·H_hi + P_hi·H_lo ----
#pragma unroll
            for (int nc = 0; nc < 8; nc++) {
                const int n = nc * 8 + g;           // B col (feature)
                const char* rH = hh + n * 144 + qt * 4 + kc * 32;
                const char* rL = hl + n * 144 + qt * 4 + kc * 32;
                const uint32_t bh0 = *(const uint32_t*)(rH);
                const uint32_t bh1 = *(const uint32_t*)(rH + 16);
                const uint32_t bl0 = *(const uint32_t*)(rL);
                const uint32_t bl1 = *(const uint32_t*)(rL + 16);
                mma16816(accs[nc], aH, bh0, bh1);
                mma16816(accs[nc], aL, bh0, bh1);
                mma16816(accs[nc], aH, bl0, bl1);
            }
        }
        __syncthreads();                // reads of buf tt&1 done before next
                                        // iteration's prefetch targets it
    }

    // ---- store partial l (quad-reduced) and partial D ----
    l0 += __shfl_xor_sync(0xffffffffu, l0, 1);
    l0 += __shfl_xor_sync(0xffffffffu, l0, 2);
    l1 += __shfl_xor_sync(0xffffffffu, l1, 1);
    l1 += __shfl_xor_sync(0xffffffffu, l1, 2);
    if (qt == 0) {
        g_pl[(size_t)js * B_ * N_ + b * N_ + row0 + i0] = l0;
        g_pl[(size_t)js * B_ * N_ + b * N_ + row0 + i1] = l1;
    }

#pragma unroll
    for (int half = 0; half < 2; half++) {
        const int row = row0 + (half ? i1 : i0);
        float* pp = g_pd + (((size_t)js * B_ + b) * N_ + row) * FOUT_;
#pragma unroll
        for (int nc = 0; nc < 8; nc++) {
            const int col = nc * 8 + 2 * qt;
            *(float2*)(pp + col) =
                make_float2(accs[nc][half * 2 + 0], accs[nc][half * 2 + 1]);
        }
    }
}

// ---------------------------------------------------------------------------
// Kernel 3: combine 4 partials -> softmax divide -> LayerNorm -> ELU -> out
// block 256 = 32 rows x 8 threads/row (8 cols each); grid 512.
// ---------------------------------------------------------------------------
__global__ void __launch_bounds__(256)
gat_epilogue_kernel(const float* __restrict__ gamma,
                    const float* __restrict__ beta,
                    float*       __restrict__ out) {
    const int tid   = threadIdx.x;
    const int rloc  = tid >> 3;                   // 0..31
    const int l8    = tid & 7;                    // 0..7
    const int grow  = blockIdx.x * 32 + rloc;     // global row id (b*N+row)

    const size_t base = (size_t)grow * FOUT_ + l8 * 8;

    float v[8];
#pragma unroll
    for (int c = 0; c < 8; c++) v[c] = 0.f;
    float l = 0.f;
#pragma unroll
    for (int s = 0; s < NSPL; s++) {
        const float4 da = *(const float4*)(g_pd + (size_t)s * B_ * N_ * FOUT_ + base);
        const float4 db = *(const float4*)(g_pd + (size_t)s * B_ * N_ * FOUT_ + base + 4);
        v[0] += da.x; v[1] += da.y; v[2] += da.z; v[3] += da.w;
        v[4] += db.x; v[5] += db.y; v[6] += db.z; v[7] += db.w;
        l += g_pl[s * B_ * N_ + grow];
    }
    const float inv = 1.f / l;
#pragma unroll
    for (int c = 0; c < 8; c++) v[c] *= inv;

    float s = 0.f;
#pragma unroll
    for (int c = 0; c < 8; c++) s += v[c];
    s += __shfl_xor_sync(0xffffffffu, s, 1);
    s += __shfl_xor_sync(0xffffffffu, s, 2);
    s += __shfl_xor_sync(0xffffffffu, s, 4);
    const float mu = s * (1.0f / FOUT_);

    float q = 0.f;
#pragma unroll
    for (int c = 0; c < 8; c++) { const float d = v[c] - mu; q += d * d; }
    q += __shfl_xor_sync(0xffffffffu, q, 1);
    q += __shfl_xor_sync(0xffffffffu, q, 2);
    q += __shfl_xor_sync(0xffffffffu, q, 4);
    const float rstd = rsqrtf(q * (1.0f / FOUT_) + 1e-5f);

    const float4 g0 = *(const float4*)(gamma + l8 * 8);
    const float4 g1 = *(const float4*)(gamma + l8 * 8 + 4);
    const float4 b0 = *(const float4*)(beta  + l8 * 8);
    const float4 b1 = *(const float4*)(beta  + l8 * 8 + 4);

    float y[8];
    y[0] = (v[0] - mu) * rstd * g0.x + b0.x;
    y[1] = (v[1] - mu) * rstd * g0.y + b0.y;
    y[2] = (v[2] - mu) * rstd * g0.z + b0.z;
    y[3] = (v[3] - mu) * rstd * g0.w + b0.w;
    y[4] = (v[4] - mu) * rstd * g1.x + b1.x;
    y[5] = (v[5] - mu) * rstd * g1.y + b1.y;
    y[6] = (v[6] - mu) * rstd * g1.z + b1.z;
    y[7] = (v[7] - mu) * rstd * g1.w + b1.w;

    float4 oa, ob;
    oa.x = y[0] > 0.f ? y[0] : expm1f(y[0]);
    oa.y = y[1] > 0.f ? y[1] : expm1f(y[1]);
    oa.z = y[2] > 0.f ? y[2] : expm1f(y[2]);
    oa.w = y[3] > 0.f ? y[3] : expm1f(y[3]);
    ob.x = y[4] > 0.f ? y[4] : expm1f(y[4]);
    ob.y = y[5] > 0.f ? y[5] : expm1f(y[5]);
    ob.z = y[6] > 0.f ? y[6] : expm1f(y[6]);
    ob.w = y[7] > 0.f ? y[7] : expm1f(y[7]);

    *(float4*)(out + base)     = oa;
    *(float4*)(out + base + 4) = ob;
}

// ---------------------------------------------------------------------------
extern "C" void kernel_launch(void* const* d_in, const int* in_sizes, int n_in,
                              void* d_out, int out_size) {
    const float* x     = (const float*)d_in[0];
    const int*   adj   = (const int*)  d_in[1];
    const float* W     = (const float*)d_in[2];
    const float* a     = (const float*)d_in[3];
    const float* gamma = (const float*)d_in[4];
    const float* beta  = (const float*)d_in[5];
    float* out = (float*)d_out;

    cudaFuncSetAttribute(gat_h_kernel,
                         cudaFuncAttributeMaxDynamicSharedMemorySize, 49152);
    cudaFuncSetAttribute(gat_attn_kernel,
                         cudaFuncAttributeMaxDynamicSharedMemorySize, SMEM2);

    gat_h_kernel<<<(B_ * N_) / 32, 256, 49152>>>(x, W, a);
    gat_attn_kernel<<<dim3(N_ / MR, B_, NSPL), 256, SMEM2>>>(adj);
    gat_epilogue_kernel<<<(B_ * N_) / 32, 256>>>(gamma, beta, out);
}

// round 11
// speedup vs baseline: 1.0906x; 1.0906x over previous
#include <cuda_runtime.h>
#include <cuda_bf16.h>
#include <cstdint>

#define B_    8
#define N_    2048
#define FIN_  128
#define FOUT_ 64
#define TJ    64
#define NT    (N_ / TJ)      // 32 tiles
#define NSPL  4              // j-splits
#define NTS   (NT / NSPL)    // 8 tiles per split
#define MR    128            // i-rows per CTA
#define LOG2E 1.4426950408889634f

// ---------------- global scratch (no allocations allowed) ----------------
__device__ __align__(16) float         g_s1[B_ * N_];                // pre-scaled LOG2E
__device__ __align__(16) float         g_s2[B_ * N_];                // pre-scaled LOG2E
__device__ __align__(16) __nv_bfloat16 g_hT_hi[B_ * FOUT_ * N_];     // [b][f][n]
__device__ __align__(16) __nv_bfloat16 g_hT_lo[B_ * FOUT_ * N_];
__device__ __align__(16) float         g_pd[NSPL * B_ * N_ * FOUT_]; // partial D (16MB)
__device__ __align__(16) float         g_pl[NSPL * B_ * N_];         // partial l

// ---------------- helpers ----------------
__device__ __forceinline__ uint32_t pack_bf16(float a, float b) {
    __nv_bfloat162 t = __float22bfloat162_rn(make_float2(a, b));
    return *reinterpret_cast<uint32_t*>(&t);
}
__device__ __forceinline__ uint32_t lo_pack(float a, float b, uint32_t hi) {
    const float ha = __uint_as_float(hi << 16);
    const float hb = __uint_as_float(hi & 0xFFFF0000u);
    return pack_bf16(a - ha, b - hb);
}
__device__ __forceinline__ void cp16(uint32_t s, const void* g) {
    asm volatile("cp.async.cg.shared.global [%0], [%1], 16;" :: "r"(s), "l"(g));
}
__device__ __forceinline__ void cp_commit() {
    asm volatile("cp.async.commit_group;" ::: "memory");
}
__device__ __forceinline__ void cp_wait0() {
    asm volatile("cp.async.wait_group 0;" ::: "memory");
}
__device__ __forceinline__ uint32_t smem_u32(const void* p) {
    uint32_t a;
    asm("{ .reg .u64 t; cvta.to.shared.u64 t, %1; cvt.u32.u64 %0, t; }" : "=r"(a) : "l"(p));
    return a;
}
__device__ __forceinline__ void ldm_x4(uint32_t* r, uint32_t addr) {
    asm volatile("ldmatrix.sync.aligned.m8n8.x4.shared.b16 {%0,%1,%2,%3}, [%4];"
                 : "=r"(r[0]), "=r"(r[1]), "=r"(r[2]), "=r"(r[3]) : "r"(addr));
}
__device__ __forceinline__ void mma16816(float* d, const uint32_t* a,
                                         uint32_t b0, uint32_t b1) {
    asm volatile(
        "mma.sync.aligned.m16n8k16.row.col.f32.bf16.bf16.f32 "
        "{%0,%1,%2,%3}, {%4,%5,%6,%7}, {%8,%9}, {%0,%1,%2,%3};"
        : "+f"(d[0]), "+f"(d[1]), "+f"(d[2]), "+f"(d[3])
        : "r"(a[0]), "r"(a[1]), "r"(a[2]), "r"(a[3]), "r"(b0), "r"(b1));
}
// masked softmax numerator; e pre-scaled by LOG2E
__device__ __forceinline__ float pv(int av, float e) {
    e = fmaxf(e, 0.2f * e);
    float r;
    asm("ex2.approx.ftz.f32 %0, %1;" : "=f"(r) : "f"(e));
    return av ? r : 0.f;
}
__device__ __forceinline__ void pf_l2(const void* p) {
    asm volatile("prefetch.global.L2 [%0];" :: "l"(p));
}

// ---------------------------------------------------------------------------
// Kernel 1: h = x@W -> hT_hi/hT_lo (bf16, [b][f][n]) + s1,s2 (x LOG2E)
// 256 threads, 64 rows/block (R9 version; 14.1us measured).
// ---------------------------------------------------------------------------
__global__ void __launch_bounds__(256)
gat_h_kernel(const float* __restrict__ x,
             const float* __restrict__ W,
             const float* __restrict__ a) {
    extern __shared__ float sm1[];
    float* Wsm = sm1;            // [128*64]  32KB
    float* xsm = sm1 + 8192;     // [64*128]  32KB
    float* hsm = xsm;            // reuse: [64][69]

    const int tid   = threadIdx.x;
    const int row0g = blockIdx.x * 64;
    const int b     = row0g >> 11;
    const int n0    = row0g & (N_ - 1);

    {
        const float4* src = (const float4*)W;
        float4* dst = (float4*)Wsm;
#pragma unroll
        for (int i = 0; i < 8; i++) dst[tid + 256 * i] = src[tid + 256 * i];
    }
    {
        const float4* src = (const float4*)(x + (size_t)row0g * FIN_);
        float4* dst = (float4*)xsm;
#pragma unroll
        for (int i = 0; i < 8; i++) dst[tid + 256 * i] = src[tid + 256 * i];
    }
    __syncthreads();

    const int r  = tid >> 4;      // 0..15
    const int cg = tid & 15;

    float4 acc[4];
#pragma unroll
    for (int q = 0; q < 4; q++) acc[q] = make_float4(0.f, 0.f, 0.f, 0.f);
#pragma unroll 4
    for (int k = 0; k < FIN_; k++) {
        const float4 w4 = *(const float4*)(Wsm + k * FOUT_ + cg * 4);
#pragma unroll
        for (int q = 0; q < 4; q++) {
            const float xv = xsm[(r + 16 * q) * FIN_ + k];
            acc[q].x += xv * w4.x; acc[q].y += xv * w4.y;
            acc[q].z += xv * w4.z; acc[q].w += xv * w4.w;
        }
    }

    const float4 a1 = *(const float4*)(a + cg * 4);
    const float4 a2 = *(const float4*)(a + FOUT_ + cg * 4);
#pragma unroll
    for (int q = 0; q < 4; q++) {
        const int row = row0g + 16 * q + r;
        float s1 = acc[q].x * a1.x + acc[q].y * a1.y + acc[q].z * a1.z + acc[q].w * a1.w;
        float s2 = acc[q].x * a2.x + acc[q].y * a2.y + acc[q].z * a2.z + acc[q].w * a2.w;
#pragma unroll
        for (int m = 8; m >= 1; m >>= 1) {
            s1 += __shfl_xor_sync(0xffffffffu, s1, m);
            s2 += __shfl_xor_sync(0xffffffffu, s2, m);
        }
        if (cg == 0) { g_s1[row] = s1 * LOG2E; g_s2[row] = s2 * LOG2E; }
    }

    __syncthreads();     // xsm reads done; reuse as hsm [64][69]
#pragma unroll
    for (int q = 0; q < 4; q++) {
        float* hp = hsm + (16 * q + r) * 69 + cg * 4;
        hp[0] = acc[q].x; hp[1] = acc[q].y; hp[2] = acc[q].z; hp[3] = acc[q].w;
    }
    __syncthreads();

    // transpose + hi/lo bf16 split: thread -> (f = tid>>2, 2 passes of 8 n)
    const int f  = tid >> 2;      // 0..63
    const int jq = tid & 3;
#pragma unroll
    for (int pass = 0; pass < 2; pass++) {
        const int nb = pass * 32 + jq * 8;
        float v[8];
#pragma unroll
        for (int u = 0; u < 8; u++) v[u] = hsm[(nb + u) * 69 + f];

        uint4 hiv, lov;
        uint32_t* hp = (uint32_t*)&hiv;
        uint32_t* lp = (uint32_t*)&lov;
#pragma unroll
        for (int q = 0; q < 4; q++) {
            hp[q] = pack_bf16(v[2 * q], v[2 * q + 1]);
            lp[q] = lo_pack(v[2 * q], v[2 * q + 1], hp[q]);
        }
        const size_t o = ((size_t)(b * FOUT_ + f)) * N_ + n0 + nb;
        *(uint4*)(g_hT_hi + o) = hiv;
        *(uint4*)(g_hT_lo + o) = lov;
    }
}

// ---------------------------------------------------------------------------
// Kernel 2: fused mask/softmax (no-max) -> HMMA hi/lo P·V, j-split partials
// 256 threads = 8 warps x 16 i-rows; grid (16, 8, 4) = 512 CTAs.
// adj read via direct LDG (no smem); h tiles cp.async double-buffered.
// smem (bytes):
#define HH_OFF   0u          // hT_hi [2][64][72] bf16  (18432; row stride 144B)
#define HL_OFF   18432u      // hT_lo                    (18432)
#define S2_OFF   36864u      // s2    [2][64] f32        (512)
#define SMEM2    37376u
// ---------------------------------------------------------------------------
__global__ void __launch_bounds__(256, 3)
gat_attn_kernel(const int* __restrict__ adj) {
    extern __shared__ char smem[];
    const uint32_t sb = smem_u32(smem);

    const int b    = blockIdx.y;
    const int row0 = blockIdx.x * MR;
    const int js   = blockIdx.z;
    const int t0   = js * NTS;
    const int tid  = threadIdx.x;
    const int w    = tid >> 5;
    const int lane = tid & 31;
    const int g    = lane >> 2;                 // 0..7 (row in frag)
    const int qt   = lane & 3;                  // 0..3 (k group in frag)

    const int i0 = w * 16 + g;                  // local rows owned by this lane
    const int i1 = i0 + 8;
    const int* arow0 = adj + (size_t)b * N_ * N_ + (size_t)(row0 + i0) * N_;
    const int* arow1 = adj + (size_t)b * N_ * N_ + (size_t)(row0 + i1) * N_;

    // ldmatrix per-lane row/quadrant offset within a B tile
    const uint32_t lmoff = (uint32_t)((lane & 7) * 144 + ((lane >> 3) & 3) * 16);

    auto prefetch = [&](int t, int buf) {
        const uint32_t hb = sb + (uint32_t)buf * 9216u;
#pragma unroll
        for (int k = 0; k < 2; k++) {
            const int c = tid + 256 * k;        // 512 chunks of 16B
            const int f = c >> 3, jc = c & 7;
            const size_t go = ((size_t)(b * FOUT_ + f)) * N_ + t * TJ + jc * 8;
            const uint32_t so = (uint32_t)(f * 144 + jc * 16);
            cp16(hb + HH_OFF + so, g_hT_hi + go);
            cp16(hb + HL_OFF + so, g_hT_lo + go);
        }
        if (tid < 16)
            cp16(sb + S2_OFF + (uint32_t)buf * 256u + tid * 16,
                 g_s2 + b * N_ + t * TJ + tid * 4);
        // L2 prefetch next adj tile rows (2 lines per row)
        if (qt == 0) {
            pf_l2(arow0 + t * TJ);  pf_l2(arow0 + t * TJ + 32);
            pf_l2(arow1 + t * TJ);  pf_l2(arow1 + t * TJ + 32);
        }
    };

    prefetch(t0, 0);
    cp_commit();

    const float s10 = g_s1[b * N_ + row0 + i0];
    const float s11 = g_s1[b * N_ + row0 + i1];

    float accs[8][4];
#pragma unroll
    for (int nc = 0; nc < 8; nc++)
#pragma unroll
        for (int q = 0; q < 4; q++) accs[nc][q] = 0.f;
    float l0 = 0.f, l1 = 0.f;

    for (int tt = 0; tt < NTS; tt++) {
        cp_wait0();
        __syncthreads();                        // h tile tt visible; buf (tt+1)&1 free
        if (tt + 1 < NTS) { prefetch(t0 + tt + 1, (tt + 1) & 1); cp_commit(); }

        const int    jg  = (t0 + tt) * TJ;
        const float* s2t = (const float*)(smem + S2_OFF + (tt & 1) * 256);
        const uint32_t hhB = sb + HH_OFF + (uint32_t)(tt & 1) * 9216u;
        const uint32_t hlB = sb + HL_OFF + (uint32_t)(tt & 1) * 9216u;

#pragma unroll
        for (int kcp = 0; kcp < 2; kcp++) {
            // ---- Phase A(kcp): p for kc = 2kcp, 2kcp+1 into A frags ----
            uint32_t aH[8], aL[8];
#pragma unroll
            for (int kk = 0; kk < 2; kk++) {
                const int kc = kcp * 2 + kk;
                const int jb = kc * 16 + 2 * qt;
                const float2 s2a = *(const float2*)(s2t + jb);
                const float2 s2b = *(const float2*)(s2t + jb + 8);
                const int2 A00 = *(const int2*)(arow0 + jg + jb);
                const int2 A08 = *(const int2*)(arow0 + jg + jb + 8);
                const int2 A10 = *(const int2*)(arow1 + jg + jb);
                const int2 A18 = *(const int2*)(arow1 + jg + jb + 8);

                const float p00 = pv(A00.x, s10 + s2a.x);
                const float p01 = pv(A00.y, s10 + s2a.y);
                const float p02 = pv(A08.x, s10 + s2b.x);
                const float p03 = pv(A08.y, s10 + s2b.y);
                const float p10 = pv(A10.x, s11 + s2a.x);
                const float p11 = pv(A10.y, s11 + s2a.y);
                const float p12 = pv(A18.x, s11 + s2b.x);
                const float p13 = pv(A18.y, s11 + s2b.y);

                l0 += (p00 + p01) + (p02 + p03);
                l1 += (p10 + p11) + (p12 + p13);

                aH[kk * 4 + 0] = pack_bf16(p00, p01);
                aH[kk * 4 + 1] = pack_bf16(p10, p11);
                aH[kk * 4 + 2] = pack_bf16(p02, p03);
                aH[kk * 4 + 3] = pack_bf16(p12, p13);
                aL[kk * 4 + 0] = lo_pack(p00, p01, aH[kk * 4 + 0]);
                aL[kk * 4 + 1] = lo_pack(p10, p11, aH[kk * 4 + 1]);
                aL[kk * 4 + 2] = lo_pack(p02, p03, aH[kk * 4 + 2]);
                aL[kk * 4 + 3] = lo_pack(p12, p13, aH[kk * 4 + 3]);
            }

            // ---- Phase B(kcp): ldmatrix B frags + 6 MMAs per nc ----
            const uint32_t kb = (uint32_t)(kcp * 64) + lmoff;
#pragma unroll
            for (int nc = 0; nc < 8; nc++) {
                uint32_t bh[4], bl[4];
                ldm_x4(bh, hhB + (uint32_t)(nc * 8 * 144) + kb);
                ldm_x4(bl, hlB + (uint32_t)(nc * 8 * 144) + kb);
                mma16816(accs[nc], aH + 0, bh[0], bh[1]);
                mma16816(accs[nc], aH + 4, bh[2], bh[3]);
                mma16816(accs[nc], aL + 0, bh[0], bh[1]);
                mma16816(accs[nc], aL + 4, bh[2], bh[3]);
                mma16816(accs[nc], aH + 0, bl[0], bl[1]);
                mma16816(accs[nc], aH + 4, bl[2], bl[3]);
            }
        }
    }

    // ---- store partial l (quad-reduced) and partial D ----
    l0 += __shfl_xor_sync(0xffffffffu, l0, 1);
    l0 += __shfl_xor_sync(0xffffffffu, l0, 2);
    l1 += __shfl_xor_sync(0xffffffffu, l1, 1);
    l1 += __shfl_xor_sync(0xffffffffu, l1, 2);
    if (qt == 0) {
        g_pl[(size_t)js * B_ * N_ + b * N_ + row0 + i0] = l0;
        g_pl[(size_t)js * B_ * N_ + b * N_ + row0 + i1] = l1;
    }

#pragma unroll
    for (int half = 0; half < 2; half++) {
        const int row = row0 + (half ? i1 : i0);
        float* pp = g_pd + (((size_t)js * B_ + b) * N_ + row) * FOUT_;
#pragma unroll
        for (int nc = 0; nc < 8; nc++) {
            const int col = nc * 8 + 2 * qt;
            *(float2*)(pp + col) =
                make_float2(accs[nc][half * 2 + 0], accs[nc][half * 2 + 1]);
        }
    }
}

// ---------------------------------------------------------------------------
// Kernel 3: combine NSPL partials -> softmax divide -> LN -> ELU -> out
// ---------------------------------------------------------------------------
__global__ void __launch_bounds__(256)
gat_epilogue_kernel(const float* __restrict__ gamma,
                    const float* __restrict__ beta,
                    float*       __restrict__ out) {
    const int tid   = threadIdx.x;
    const int rloc  = tid >> 3;                   // 0..31
    const int l8    = tid & 7;                    // 0..7
    const int grow  = blockIdx.x * 32 + rloc;

    const size_t base = (size_t)grow * FOUT_ + l8 * 8;

    float v[8];
#pragma unroll
    for (int c = 0; c < 8; c++) v[c] = 0.f;
    float l = 0.f;
#pragma unroll
    for (int s = 0; s < NSPL; s++) {
        const float4 da = *(const float4*)(g_pd + (size_t)s * B_ * N_ * FOUT_ + base);
        const float4 db = *(const float4*)(g_pd + (size_t)s * B_ * N_ * FOUT_ + base + 4);
        v[0] += da.x; v[1] += da.y; v[2] += da.z; v[3] += da.w;
        v[4] += db.x; v[5] += db.y; v[6] += db.z; v[7] += db.w;
        l += g_pl[s * B_ * N_ + grow];
    }
    const float inv = 1.f / l;
#pragma unroll
    for (int c = 0; c < 8; c++) v[c] *= inv;

    float s = 0.f;
#pragma unroll
    for (int c = 0; c < 8; c++) s += v[c];
    s += __shfl_xor_sync(0xffffffffu, s, 1);
    s += __shfl_xor_sync(0xffffffffu, s, 2);
    s += __shfl_xor_sync(0xffffffffu, s, 4);
    const float mu = s * (1.0f / FOUT_);

    float q = 0.f;
#pragma unroll
    for (int c = 0; c < 8; c++) { const float d = v[c] - mu; q += d * d; }
    q += __shfl_xor_sync(0xffffffffu, q, 1);
    q += __shfl_xor_sync(0xffffffffu, q, 2);
    q += __shfl_xor_sync(0xffffffffu, q, 4);
    const float rstd = rsqrtf(q * (1.0f / FOUT_) + 1e-5f);

    const float4 g0 = *(const float4*)(gamma + l8 * 8);
    const float4 g1 = *(const float4*)(gamma + l8 * 8 + 4);
    const float4 b0 = *(const float4*)(beta  + l8 * 8);
    const float4 b1 = *(const float4*)(beta  + l8 * 8 + 4);

    float y[8];
    y[0] = (v[0] - mu) * rstd * g0.x + b0.x;
    y[1] = (v[1] - mu) * rstd * g0.y + b0.y;
    y[2] = (v[2] - mu) * rstd * g0.z + b0.z;
    y[3] = (v[3] - mu) * rstd * g0.w + b0.w;
    y[4] = (v[4] - mu) * rstd * g1.x + b1.x;
    y[5] = (v[5] - mu) * rstd * g1.y + b1.y;
    y[6] = (v[6] - mu) * rstd * g1.z + b1.z;
    y[7] = (v[7] - mu) * rstd * g1.w + b1.w;

    float4 oa, ob;
    oa.x = y[0] > 0.f ? y[0] : expm1f(y[0]);
    oa.y = y[1] > 0.f ? y[1] : expm1f(y[1]);
    oa.z = y[2] > 0.f ? y[2] : expm1f(y[2]);
    oa.w = y[3] > 0.f ? y[3] : expm1f(y[3]);
    ob.x = y[4] > 0.f ? y[4] : expm1f(y[4]);
    ob.y = y[5] > 0.f ? y[5] : expm1f(y[5]);
    ob.z = y[6] > 0.f ? y[6] : expm1f(y[6]);
    ob.w = y[7] > 0.f ? y[7] : expm1f(y[7]);

    *(float4*)(out + base)     = oa;
    *(float4*)(out + base + 4) = ob;
}

// ---------------------------------------------------------------------------
extern "C" void kernel_launch(void* const* d_in, const int* in_sizes, int n_in,
                              void* d_out, int out_size) {
    const float* x     = (const float*)d_in[0];
    const int*   adj   = (const int*)  d_in[1];
    const float* W     = (const float*)d_in[2];
    const float* a     = (const float*)d_in[3];
    const float* gamma = (const float*)d_in[4];
    const float* beta  = (const float*)d_in[5];
    float* out = (float*)d_out;

    cudaFuncSetAttribute(gat_h_kernel,
                         cudaFuncAttributeMaxDynamicSharedMemorySize, 65536);
    cudaFuncSetAttribute(gat_attn_kernel,
                         cudaFuncAttributeMaxDynamicSharedMemorySize, SMEM2);

    gat_h_kernel<<<(B_ * N_) / 64, 256, 65536>>>(x, W, a);
    gat_attn_kernel<<<dim3(N_ / MR, B_, NSPL), 256, SMEM2>>>(adj);
    gat_epilogue_kernel<<<(B_ * N_) / 32, 256>>>(gamma, beta, out);
}